// round 5
// baseline (speedup 1.0000x reference)
#include <cuda_runtime.h>
#include <cuda_bf16.h>
#include <cstdint>
#include <cstddef>

// ============================================================================
// BitLinear via int8 IMMA:
//   out[m,n] = (sum_k qx[m,k]*t[n,k]) * s_tok[m] * s_w
//   qx in [-8,7] int8, t in {-1,0,1} int8. int32 accumulation is exact.
// ============================================================================

static constexpr int MDIM = 8192;
static constexpr int NDIM = 16384;
static constexpr int KDIM = 4096;
static constexpr float EPSV = 1e-5f;

__device__ __align__(128) int8_t g_qx[(size_t)MDIM * KDIM];   // 33.5 MB
__device__ __align__(128) int8_t g_wq[(size_t)NDIM * KDIM];   // 67 MB
__device__ float g_st[MDIM];                                  // s_tok * s_w
__device__ float g_partial[2048];
__device__ float g_wscale;

__device__ __forceinline__ uint32_t smem_u32(const void* p) {
    uint32_t a;
    asm("{ .reg .u64 t; cvta.to.shared.u64 t, %1; cvt.u32.u64 %0, t; }" : "=r"(a) : "l"(p));
    return a;
}

// ---------------------------------------------------------------------------
// Weight scale: two-pass deterministic mean(|w|)
// ---------------------------------------------------------------------------
__global__ void wsum_kernel(const float* __restrict__ w) {
    __shared__ float red[256];
    const float4* w4 = reinterpret_cast<const float4*>(w);
    const size_t n4 = (size_t)NDIM * KDIM / 4;
    float s = 0.f;
    for (size_t i = (size_t)blockIdx.x * 256 + threadIdx.x; i < n4; i += (size_t)2048 * 256) {
        float4 v = w4[i];
        s += fabsf(v.x) + fabsf(v.y) + fabsf(v.z) + fabsf(v.w);
    }
    red[threadIdx.x] = s;
    __syncthreads();
    for (int off = 128; off > 0; off >>= 1) {
        if (threadIdx.x < off) red[threadIdx.x] += red[threadIdx.x + off];
        __syncthreads();
    }
    if (threadIdx.x == 0) g_partial[blockIdx.x] = red[0];
}

__global__ void wscale_kernel() {
    __shared__ float red[1024];
    red[threadIdx.x] = g_partial[threadIdx.x] + g_partial[threadIdx.x + 1024];
    __syncthreads();
    for (int off = 512; off > 0; off >>= 1) {
        if (threadIdx.x < off) red[threadIdx.x] += red[threadIdx.x + off];
        __syncthreads();
    }
    if (threadIdx.x == 0)
        g_wscale = fmaxf(red[0] / (float)((size_t)NDIM * KDIM), EPSV);
}

// ---------------------------------------------------------------------------
// Weight ternarize -> int8 {-1,0,1}
// ---------------------------------------------------------------------------
__global__ void wquant_kernel(const float* __restrict__ w) {
    const float sc = g_wscale;
    const float4* w4 = reinterpret_cast<const float4*>(w);
    uchar4* o4 = reinterpret_cast<uchar4*>(g_wq);
    const size_t n4 = (size_t)NDIM * KDIM / 4;
    for (size_t i = (size_t)blockIdx.x * blockDim.x + threadIdx.x; i < n4;
         i += (size_t)gridDim.x * blockDim.x) {
        float4 v = w4[i];
        int a = (int)fminf(fmaxf(rintf(v.x / sc), -1.f), 1.f);
        int b = (int)fminf(fmaxf(rintf(v.y / sc), -1.f), 1.f);
        int c = (int)fminf(fmaxf(rintf(v.z / sc), -1.f), 1.f);
        int d = (int)fminf(fmaxf(rintf(v.w / sc), -1.f), 1.f);
        o4[i] = make_uchar4((uint8_t)(int8_t)a, (uint8_t)(int8_t)b,
                            (uint8_t)(int8_t)c, (uint8_t)(int8_t)d);
    }
}

// ---------------------------------------------------------------------------
// Activation quant: per-token absmax -> int8 in [-8,7]
// ---------------------------------------------------------------------------
__global__ void xquant_kernel(const float* __restrict__ x) {
    __shared__ float red[256];
    __shared__ float s_sh;
    const int t = blockIdx.x;
    const float4* xr = reinterpret_cast<const float4*>(x + (size_t)t * KDIM);
    float4 v[4];
    float mx = 0.f;
#pragma unroll
    for (int j = 0; j < 4; j++) {
        v[j] = xr[j * 256 + threadIdx.x];
        mx = fmaxf(mx, fmaxf(fmaxf(fabsf(v[j].x), fabsf(v[j].y)),
                             fmaxf(fabsf(v[j].z), fabsf(v[j].w))));
    }
    red[threadIdx.x] = mx;
    __syncthreads();
    for (int off = 128; off > 0; off >>= 1) {
        if (threadIdx.x < off) red[threadIdx.x] = fmaxf(red[threadIdx.x], red[threadIdx.x + off]);
        __syncthreads();
    }
    if (threadIdx.x == 0) {
        float s = fmaxf(red[0], EPSV) / 7.0f;
        s_sh = s;
        g_st[t] = s * g_wscale;
    }
    __syncthreads();
    const float s = s_sh;
    uchar4* o4 = reinterpret_cast<uchar4*>(g_qx + (size_t)t * KDIM);
#pragma unroll
    for (int j = 0; j < 4; j++) {
        int i4 = j * 256 + threadIdx.x;
        int a = (int)fminf(fmaxf(rintf(v[j].x / s), -8.f), 7.f);
        int b = (int)fminf(fmaxf(rintf(v[j].y / s), -8.f), 7.f);
        int c = (int)fminf(fmaxf(rintf(v[j].z / s), -8.f), 7.f);
        int d = (int)fminf(fmaxf(rintf(v[j].w / s), -8.f), 7.f);
        o4[i4] = make_uchar4((uint8_t)(int8_t)a, (uint8_t)(int8_t)b,
                             (uint8_t)(int8_t)c, (uint8_t)(int8_t)d);
    }
}

// ---------------------------------------------------------------------------
// GEMM: out[8192,16384] = qx @ wq^T (s8 IMMA), scaled.
// BM=BN=128, BK=64, 5-stage cp.async pipeline, 8 warps (2x4), warp tile 64x32.
// 1 CTA/SM so ptxas gets the full 255-reg budget (no spills).
// ---------------------------------------------------------------------------
static constexpr int BM = 128, BN = 128, BK = 64, STAGES = 5;
static constexpr int KT = KDIM / BK;                    // 64 iters
static constexpr int STAGE_BYTES = BM * BK + BN * BK;   // 16384
static constexpr int SMEM_TOTAL = STAGES * STAGE_BYTES; // 81920

// phys chunk = chunk ^ ((row>>1)&3); offset = row*64 + phys*16
__device__ __forceinline__ uint32_t swz(int row, int chunk) {
    return (uint32_t)(row * 64 + ((chunk ^ ((row >> 1) & 3)) << 4));
}

#define LDSM_X4(R0, R1, R2, R3, ADDR)                                          \
    asm volatile("ldmatrix.sync.aligned.m8n8.x4.shared.b16 {%0,%1,%2,%3}, [%4];" \
                 : "=r"(R0), "=r"(R1), "=r"(R2), "=r"(R3) : "r"(ADDR))

#define MMA_S8(C, A, B0, B1)                                                   \
    asm volatile(                                                              \
        "mma.sync.aligned.m16n8k32.row.col.s32.s8.s8.s32 "                     \
        "{%0,%1,%2,%3}, {%4,%5,%6,%7}, {%8,%9}, {%0,%1,%2,%3};"                \
        : "+r"((C)[0]), "+r"((C)[1]), "+r"((C)[2]), "+r"((C)[3])               \
        : "r"((A)[0]), "r"((A)[1]), "r"((A)[2]), "r"((A)[3]), "r"(B0), "r"(B1))

__global__ void __launch_bounds__(256, 1)
gemm_kernel(float* __restrict__ out) {
    extern __shared__ char smem[];
    const uint32_t sb = smem_u32(smem);
    const int tid = threadIdx.x;
    const int wid = tid >> 5;
    const int lane = tid & 31;
    const int warp_m = wid >> 2;   // 0..1
    const int warp_n = wid & 3;    // 0..3

    // GROUP_M=8 rasterization
    const int num_n = NDIM / BN;   // 128
    int pid = blockIdx.x;
    int group = pid / (8 * num_n);
    int pid_m = group * 8 + (pid % 8);
    int pid_n = (pid % (8 * num_n)) / 8;
    const int m_base = pid_m * BM;
    const int n_base = pid_n * BN;

    // ---- global->smem load slots: thread handles row = tid>>1, 2 chunks ----
    const int lrow = tid >> 1;
    const int lc = (tid & 1) * 2;
    const int8_t* ga = g_qx + (size_t)(m_base + lrow) * KDIM + lc * 16;
    const int8_t* gb = g_wq + (size_t)(n_base + lrow) * KDIM + lc * 16;
    const uint32_t sa0 = swz(lrow, lc), sa1 = swz(lrow, lc + 1);

    auto load_tile = [&](int s, int k) {
        const uint32_t st = sb + s * STAGE_BYTES;
        const int8_t* a = ga + k * BK;
        const int8_t* b = gb + k * BK;
        asm volatile("cp.async.cg.shared.global [%0], [%1], 16;" :: "r"(st + sa0), "l"(a) : "memory");
        asm volatile("cp.async.cg.shared.global [%0], [%1], 16;" :: "r"(st + sa1), "l"(a + 16) : "memory");
        asm volatile("cp.async.cg.shared.global [%0], [%1], 16;" :: "r"(st + BM * BK + sa0), "l"(b) : "memory");
        asm volatile("cp.async.cg.shared.global [%0], [%1], 16;" :: "r"(st + BM * BK + sa1), "l"(b + 16) : "memory");
        asm volatile("cp.async.commit_group;" ::: "memory");
    };

    // ---- ldmatrix per-lane address components ----
    const int ra = (lane & 7) + ((lane >> 3) & 1) * 8;  // row within 16-row atom
    const int csel = lane >> 4;                          // 0/1: which 16B chunk

    uint32_t a_rowterm[4]; int a_swz[4];
#pragma unroll
    for (int i = 0; i < 4; i++) {
        int r = warp_m * 64 + i * 16 + ra;
        a_rowterm[i] = (uint32_t)(r * 64);
        a_swz[i] = (r >> 1) & 3;
    }
    uint32_t b_rowterm[2]; int b_swz[2];
#pragma unroll
    for (int j = 0; j < 2; j++) {
        int r = warp_n * 32 + j * 16 + ra;
        b_rowterm[j] = (uint32_t)(BM * BK + r * 64);
        b_swz[j] = (r >> 1) & 3;
    }

    int acc[4][4][4];
#pragma unroll
    for (int i = 0; i < 4; i++)
#pragma unroll
        for (int j = 0; j < 4; j++)
#pragma unroll
            for (int c = 0; c < 4; c++) acc[i][j][c] = 0;

    // ---- prologue: fill STAGES-1 = 4 stages ----
#pragma unroll
    for (int p = 0; p < STAGES - 1; p++) load_tile(p, p);

    int stage_c = 0, stage_p = STAGES - 1;
    for (int k = 0; k < KT; k++) {
        asm volatile("cp.async.wait_group %0;" :: "n"(STAGES - 2) : "memory");
        __syncthreads();

        // issue next stage (uniform commit count keeps wait_group exact)
        if (k + STAGES - 1 < KT) load_tile(stage_p, k + STAGES - 1);
        else asm volatile("cp.async.commit_group;" ::: "memory");
        if (++stage_p == STAGES) stage_p = 0;

        const uint32_t st = sb + stage_c * STAGE_BYTES;
        if (++stage_c == STAGES) stage_c = 0;
#pragma unroll
        for (int ks = 0; ks < 2; ks++) {
            const int cbase = ks * 2 + csel;
            uint32_t afr[4][4];
#pragma unroll
            for (int i = 0; i < 4; i++) {
                uint32_t addr = st + a_rowterm[i] + (uint32_t)((cbase ^ a_swz[i]) << 4);
                LDSM_X4(afr[i][0], afr[i][1], afr[i][2], afr[i][3], addr);
            }
            uint32_t bfr[2][4];
#pragma unroll
            for (int j = 0; j < 2; j++) {
                uint32_t addr = st + b_rowterm[j] + (uint32_t)((cbase ^ b_swz[j]) << 4);
                LDSM_X4(bfr[j][0], bfr[j][1], bfr[j][2], bfr[j][3], addr);
            }
#pragma unroll
            for (int i = 0; i < 4; i++) {
#pragma unroll
                for (int j = 0; j < 2; j++) {
                    MMA_S8(acc[i][2 * j],     afr[i], bfr[j][0], bfr[j][2]);
                    MMA_S8(acc[i][2 * j + 1], afr[i], bfr[j][1], bfr[j][3]);
                }
            }
        }
    }

    // ---- epilogue: int32 -> f32 * s_tok*s_w, f32x2 stores ----
#pragma unroll
    for (int i = 0; i < 4; i++) {
        const int r0 = m_base + warp_m * 64 + i * 16 + (lane >> 2);
        const int r1 = r0 + 8;
        const float st0 = g_st[r0];
        const float st1 = g_st[r1];
        float* o0 = out + (size_t)r0 * NDIM + n_base + warp_n * 32 + (lane & 3) * 2;
        float* o1 = out + (size_t)r1 * NDIM + n_base + warp_n * 32 + (lane & 3) * 2;
#pragma unroll
        for (int j = 0; j < 4; j++) {
            float2 v0 = make_float2((float)acc[i][j][0] * st0, (float)acc[i][j][1] * st0);
            float2 v1 = make_float2((float)acc[i][j][2] * st1, (float)acc[i][j][3] * st1);
            *reinterpret_cast<float2*>(o0 + j * 8) = v0;
            *reinterpret_cast<float2*>(o1 + j * 8) = v1;
        }
    }
}

// ---------------------------------------------------------------------------
extern "C" void kernel_launch(void* const* d_in, const int* in_sizes, int n_in,
                              void* d_out, int out_size) {
    const float* x = (const float*)d_in[0];
    const float* w = (const float*)d_in[1];
    if (n_in >= 2 && in_sizes[0] > in_sizes[1]) {  // x is 33.5M elems, w is 67M
        const float* t = x; x = w; w = t;
    }
    float* out = (float*)d_out;

    wsum_kernel<<<2048, 256>>>(w);
    wscale_kernel<<<1, 1024>>>();
    wquant_kernel<<<8192, 256>>>(w);
    xquant_kernel<<<MDIM, 256>>>(x);

    cudaFuncSetAttribute(gemm_kernel, cudaFuncAttributeMaxDynamicSharedMemorySize, SMEM_TOTAL);
    gemm_kernel<<<(MDIM / BM) * (NDIM / BN), 256, SMEM_TOTAL>>>(out);
}

// round 6
// speedup vs baseline: 1.0025x; 1.0025x over previous
#include <cuda_runtime.h>
#include <cuda_bf16.h>
#include <cstdint>
#include <cstddef>

// ============================================================================
// BitLinear via int8 IMMA:
//   out[m,n] = (sum_k qx[m,k]*t[n,k]) * s_tok[m] * s_w
//   qx in [-8,7] int8, t in {-1,0,1} int8. int32 accumulation is exact.
// ============================================================================

static constexpr int MDIM = 8192;
static constexpr int NDIM = 16384;
static constexpr int KDIM = 4096;
static constexpr float EPSV = 1e-5f;

__device__ __align__(128) int8_t g_qx[(size_t)MDIM * KDIM];   // 33.5 MB
__device__ __align__(128) int8_t g_wq[(size_t)NDIM * KDIM];   // 67 MB
__device__ float g_st[MDIM];                                  // s_tok * s_w
__device__ float g_partial[2048];

__device__ __forceinline__ uint32_t smem_u32(const void* p) {
    uint32_t a;
    asm("{ .reg .u64 t; cvta.to.shared.u64 t, %1; cvt.u32.u64 %0, t; }" : "=r"(a) : "l"(p));
    return a;
}

// Deterministic inline reduction of g_partial -> wscale. Identical code in
// every consumer block => identical float everywhere.
__device__ __forceinline__ float compute_wscale(int tid, float* red) {
    float s = 0.f;
#pragma unroll
    for (int i = 0; i < 8; i++) s += g_partial[tid + 256 * i];
    red[tid] = s;
    __syncthreads();
    for (int off = 128; off > 0; off >>= 1) {
        if (tid < off) red[tid] += red[tid + off];
        __syncthreads();
    }
    float w = fmaxf(red[0] * (1.0f / 67108864.0f), EPSV);  // / (N*K) = /2^26 exact
    __syncthreads();
    return w;
}

// ---------------------------------------------------------------------------
// Pass 1: block partials of sum(|w|)
// ---------------------------------------------------------------------------
__global__ void wsum_kernel(const float* __restrict__ w) {
    __shared__ float red[256];
    const float4* w4 = reinterpret_cast<const float4*>(w);
    const size_t n4 = (size_t)NDIM * KDIM / 4;
    float s = 0.f;
    for (size_t i = (size_t)blockIdx.x * 256 + threadIdx.x; i < n4; i += (size_t)2048 * 256) {
        float4 v = w4[i];
        s += fabsf(v.x) + fabsf(v.y) + fabsf(v.z) + fabsf(v.w);
    }
    red[threadIdx.x] = s;
    __syncthreads();
    for (int off = 128; off > 0; off >>= 1) {
        if (threadIdx.x < off) red[threadIdx.x] += red[threadIdx.x + off];
        __syncthreads();
    }
    if (threadIdx.x == 0) g_partial[blockIdx.x] = red[0];
}

// ---------------------------------------------------------------------------
// Weight ternarize -> int8 {-1,0,1} (wscale computed inline)
// ---------------------------------------------------------------------------
__global__ void wquant_kernel(const float* __restrict__ w) {
    __shared__ float red[256];
    const float sc = compute_wscale(threadIdx.x, red);
    const float4* w4 = reinterpret_cast<const float4*>(w);
    uchar4* o4 = reinterpret_cast<uchar4*>(g_wq);
    const size_t n4 = (size_t)NDIM * KDIM / 4;
    for (size_t i = (size_t)blockIdx.x * blockDim.x + threadIdx.x; i < n4;
         i += (size_t)gridDim.x * blockDim.x) {
        float4 v = w4[i];
        int a = (int)fminf(fmaxf(rintf(v.x / sc), -1.f), 1.f);
        int b = (int)fminf(fmaxf(rintf(v.y / sc), -1.f), 1.f);
        int c = (int)fminf(fmaxf(rintf(v.z / sc), -1.f), 1.f);
        int d = (int)fminf(fmaxf(rintf(v.w / sc), -1.f), 1.f);
        o4[i] = make_uchar4((uint8_t)(int8_t)a, (uint8_t)(int8_t)b,
                            (uint8_t)(int8_t)c, (uint8_t)(int8_t)d);
    }
}

// ---------------------------------------------------------------------------
// Activation quant: per-token absmax -> int8 in [-8,7] (wscale inline)
// ---------------------------------------------------------------------------
__global__ void xquant_kernel(const float* __restrict__ x) {
    __shared__ float red[256];
    __shared__ float s_sh;
    const float wsc = compute_wscale(threadIdx.x, red);
    const int t = blockIdx.x;
    const float4* xr = reinterpret_cast<const float4*>(x + (size_t)t * KDIM);
    float4 v[4];
    float mx = 0.f;
#pragma unroll
    for (int j = 0; j < 4; j++) {
        v[j] = xr[j * 256 + threadIdx.x];
        mx = fmaxf(mx, fmaxf(fmaxf(fabsf(v[j].x), fabsf(v[j].y)),
                             fmaxf(fabsf(v[j].z), fabsf(v[j].w))));
    }
    red[threadIdx.x] = mx;
    __syncthreads();
    for (int off = 128; off > 0; off >>= 1) {
        if (threadIdx.x < off) red[threadIdx.x] = fmaxf(red[threadIdx.x], red[threadIdx.x + off]);
        __syncthreads();
    }
    if (threadIdx.x == 0) {
        float s = fmaxf(red[0], EPSV) / 7.0f;
        s_sh = s;
        g_st[t] = s * wsc;
    }
    __syncthreads();
    const float s = s_sh;
    uchar4* o4 = reinterpret_cast<uchar4*>(g_qx + (size_t)t * KDIM);
#pragma unroll
    for (int j = 0; j < 4; j++) {
        int i4 = j * 256 + threadIdx.x;
        int a = (int)fminf(fmaxf(rintf(v[j].x / s), -8.f), 7.f);
        int b = (int)fminf(fmaxf(rintf(v[j].y / s), -8.f), 7.f);
        int c = (int)fminf(fmaxf(rintf(v[j].z / s), -8.f), 7.f);
        int d = (int)fminf(fmaxf(rintf(v[j].w / s), -8.f), 7.f);
        o4[i4] = make_uchar4((uint8_t)(int8_t)a, (uint8_t)(int8_t)b,
                             (uint8_t)(int8_t)c, (uint8_t)(int8_t)d);
    }
}

// ---------------------------------------------------------------------------
// GEMM half: out[:, n_off : n_off+8192] = qx @ wq^T (s8 IMMA), scaled.
// BM=BN=128, BK=64, 5-stage cp.async, 8 warps (2x4), warp tile 64x32.
// Launched twice (two N halves) so ncu's fixed capture index lands on a GEMM.
// ---------------------------------------------------------------------------
static constexpr int BM = 128, BN = 128, BK = 64, STAGES = 5;
static constexpr int KT = KDIM / BK;                    // 64 iters
static constexpr int STAGE_BYTES = BM * BK + BN * BK;   // 16384
static constexpr int SMEM_TOTAL = STAGES * STAGE_BYTES; // 81920
static constexpr int NHALF = NDIM / 2;                  // 8192

// phys chunk = chunk ^ ((row>>1)&3); offset = row*64 + phys*16
__device__ __forceinline__ uint32_t swz(int row, int chunk) {
    return (uint32_t)(row * 64 + ((chunk ^ ((row >> 1) & 3)) << 4));
}

#define LDSM_X4(R0, R1, R2, R3, ADDR)                                          \
    asm volatile("ldmatrix.sync.aligned.m8n8.x4.shared.b16 {%0,%1,%2,%3}, [%4];" \
                 : "=r"(R0), "=r"(R1), "=r"(R2), "=r"(R3) : "r"(ADDR))

#define MMA_S8(C, A, B0, B1)                                                   \
    asm volatile(                                                              \
        "mma.sync.aligned.m16n8k32.row.col.s32.s8.s8.s32 "                     \
        "{%0,%1,%2,%3}, {%4,%5,%6,%7}, {%8,%9}, {%0,%1,%2,%3};"                \
        : "+r"((C)[0]), "+r"((C)[1]), "+r"((C)[2]), "+r"((C)[3])               \
        : "r"((A)[0]), "r"((A)[1]), "r"((A)[2]), "r"((A)[3]), "r"(B0), "r"(B1))

__global__ void __launch_bounds__(256, 1)
gemm_kernel(float* __restrict__ out, int n_off) {
    extern __shared__ char smem[];
    const uint32_t sb = smem_u32(smem);
    const int tid = threadIdx.x;
    const int wid = tid >> 5;
    const int lane = tid & 31;
    const int warp_m = wid >> 2;   // 0..1
    const int warp_n = wid & 3;    // 0..3

    // GROUP_M=8 rasterization over this half's 64x64 tile grid
    const int num_n = NHALF / BN;  // 64
    int pid = blockIdx.x;
    int group = pid / (8 * num_n);
    int pid_m = group * 8 + (pid % 8);
    int pid_n = (pid % (8 * num_n)) / 8;
    const int m_base = pid_m * BM;
    const int n_base = n_off + pid_n * BN;

    // ---- global->smem load slots: thread handles row = tid>>1, 2 chunks ----
    const int lrow = tid >> 1;
    const int lc = (tid & 1) * 2;
    const int8_t* ga = g_qx + (size_t)(m_base + lrow) * KDIM + lc * 16;
    const int8_t* gb = g_wq + (size_t)(n_base + lrow) * KDIM + lc * 16;
    const uint32_t sa0 = swz(lrow, lc), sa1 = swz(lrow, lc + 1);

    auto load_tile = [&](int s, int k) {
        const uint32_t st = sb + s * STAGE_BYTES;
        const int8_t* a = ga + k * BK;
        const int8_t* b = gb + k * BK;
        asm volatile("cp.async.cg.shared.global [%0], [%1], 16;" :: "r"(st + sa0), "l"(a) : "memory");
        asm volatile("cp.async.cg.shared.global [%0], [%1], 16;" :: "r"(st + sa1), "l"(a + 16) : "memory");
        asm volatile("cp.async.cg.shared.global [%0], [%1], 16;" :: "r"(st + BM * BK + sa0), "l"(b) : "memory");
        asm volatile("cp.async.cg.shared.global [%0], [%1], 16;" :: "r"(st + BM * BK + sa1), "l"(b + 16) : "memory");
        asm volatile("cp.async.commit_group;" ::: "memory");
    };

    // ---- ldmatrix per-lane address components ----
    const int ra = (lane & 7) + ((lane >> 3) & 1) * 8;  // row within 16-row atom
    const int csel = lane >> 4;                          // 0/1: which 16B chunk

    uint32_t a_rowterm[4]; int a_swz[4];
#pragma unroll
    for (int i = 0; i < 4; i++) {
        int r = warp_m * 64 + i * 16 + ra;
        a_rowterm[i] = (uint32_t)(r * 64);
        a_swz[i] = (r >> 1) & 3;
    }
    uint32_t b_rowterm[2]; int b_swz[2];
#pragma unroll
    for (int j = 0; j < 2; j++) {
        int r = warp_n * 32 + j * 16 + ra;
        b_rowterm[j] = (uint32_t)(BM * BK + r * 64);
        b_swz[j] = (r >> 1) & 3;
    }

    int acc[4][4][4];
#pragma unroll
    for (int i = 0; i < 4; i++)
#pragma unroll
        for (int j = 0; j < 4; j++)
#pragma unroll
            for (int c = 0; c < 4; c++) acc[i][j][c] = 0;

    // ---- prologue: fill STAGES-1 = 4 stages ----
#pragma unroll
    for (int p = 0; p < STAGES - 1; p++) load_tile(p, p);

    int stage_c = 0, stage_p = STAGES - 1;
    for (int k = 0; k < KT; k++) {
        asm volatile("cp.async.wait_group %0;" :: "n"(STAGES - 2) : "memory");
        __syncthreads();

        // issue next stage (uniform commit count keeps wait_group exact)
        if (k + STAGES - 1 < KT) load_tile(stage_p, k + STAGES - 1);
        else asm volatile("cp.async.commit_group;" ::: "memory");
        if (++stage_p == STAGES) stage_p = 0;

        const uint32_t st = sb + stage_c * STAGE_BYTES;
        if (++stage_c == STAGES) stage_c = 0;
#pragma unroll
        for (int ks = 0; ks < 2; ks++) {
            const int cbase = ks * 2 + csel;
            uint32_t afr[4][4];
#pragma unroll
            for (int i = 0; i < 4; i++) {
                uint32_t addr = st + a_rowterm[i] + (uint32_t)((cbase ^ a_swz[i]) << 4);
                LDSM_X4(afr[i][0], afr[i][1], afr[i][2], afr[i][3], addr);
            }
            uint32_t bfr[2][4];
#pragma unroll
            for (int j = 0; j < 2; j++) {
                uint32_t addr = st + b_rowterm[j] + (uint32_t)((cbase ^ b_swz[j]) << 4);
                LDSM_X4(bfr[j][0], bfr[j][1], bfr[j][2], bfr[j][3], addr);
            }
#pragma unroll
            for (int i = 0; i < 4; i++) {
#pragma unroll
                for (int j = 0; j < 2; j++) {
                    MMA_S8(acc[i][2 * j],     afr[i], bfr[j][0], bfr[j][2]);
                    MMA_S8(acc[i][2 * j + 1], afr[i], bfr[j][1], bfr[j][3]);
                }
            }
        }
    }

    // ---- epilogue: int32 -> f32 * s_tok*s_w, f32x2 stores ----
#pragma unroll
    for (int i = 0; i < 4; i++) {
        const int r0 = m_base + warp_m * 64 + i * 16 + (lane >> 2);
        const int r1 = r0 + 8;
        const float st0 = g_st[r0];
        const float st1 = g_st[r1];
        float* o0 = out + (size_t)r0 * NDIM + n_base + warp_n * 32 + (lane & 3) * 2;
        float* o1 = out + (size_t)r1 * NDIM + n_base + warp_n * 32 + (lane & 3) * 2;
#pragma unroll
        for (int j = 0; j < 4; j++) {
            float2 v0 = make_float2((float)acc[i][j][0] * st0, (float)acc[i][j][1] * st0);
            float2 v1 = make_float2((float)acc[i][j][2] * st1, (float)acc[i][j][3] * st1);
            *reinterpret_cast<float2*>(o0 + j * 8) = v0;
            *reinterpret_cast<float2*>(o1 + j * 8) = v1;
        }
    }
}

// ---------------------------------------------------------------------------
extern "C" void kernel_launch(void* const* d_in, const int* in_sizes, int n_in,
                              void* d_out, int out_size) {
    const float* x = (const float*)d_in[0];
    const float* w = (const float*)d_in[1];
    if (n_in >= 2 && in_sizes[0] > in_sizes[1]) {  // x is 33.5M elems, w is 67M
        const float* t = x; x = w; w = t;
    }
    float* out = (float*)d_out;

    wsum_kernel<<<2048, 256>>>(w);
    wquant_kernel<<<8192, 256>>>(w);
    xquant_kernel<<<MDIM, 256>>>(x);

    cudaFuncSetAttribute(gemm_kernel, cudaFuncAttributeMaxDynamicSharedMemorySize, SMEM_TOTAL);
    const int half_grid = (MDIM / BM) * (NHALF / BN);   // 4096
    gemm_kernel<<<half_grid, 256, SMEM_TOTAL>>>(out, 0);
    gemm_kernel<<<half_grid, 256, SMEM_TOTAL>>>(out, NHALF);
}

// round 8
// speedup vs baseline: 1.3317x; 1.3283x over previous
#include <cuda_runtime.h>
#include <cuda_bf16.h>
#include <cstdint>
#include <cstddef>

// ============================================================================
// BitLinear: out[m,n] = (sum_k qx[m,k]*t[n,k]) * s_tok[m] * s_w
// A/B probe: N[0,8192) via bf16 mma.sync m16n8k16 (rate unknown, ncu idx 3),
//            N[8192,16384) via int8 mma.sync (known ~3.6ms/half).
// Both exact: small ints; int32 / f32 accumulation of ints is exact.
// All dynamic smem kept at 81920B (128KB requests correlate with container
// failures in rounds 3/4/7).
// ============================================================================

static constexpr int MDIM = 8192;
static constexpr int NDIM = 16384;
static constexpr int KDIM = 4096;
static constexpr int NHALF = NDIM / 2;
static constexpr float EPSV = 1e-5f;

__device__ __align__(128) int8_t        g_qx[(size_t)MDIM * KDIM];     // 33.5 MB
__device__ __align__(128) int8_t        g_wq[(size_t)NHALF * KDIM];    // 33.5 MB (w rows 8192..16383)
__device__ __align__(128) __nv_bfloat16 g_qxbf[(size_t)MDIM * KDIM];   // 67 MB
__device__ __align__(128) __nv_bfloat16 g_wqbf[(size_t)NHALF * KDIM];  // 67 MB (w rows 0..8191)
__device__ float g_st[MDIM];
__device__ float g_partial[2048];

__device__ __forceinline__ uint32_t smem_u32(const void* p) {
    uint32_t a;
    asm("{ .reg .u64 t; cvta.to.shared.u64 t, %1; cvt.u32.u64 %0, t; }" : "=r"(a) : "l"(p));
    return a;
}

// Deterministic inline reduction of g_partial -> wscale (identical in all users)
__device__ __forceinline__ float compute_wscale(int tid, float* red) {
    float s = 0.f;
#pragma unroll
    for (int i = 0; i < 8; i++) s += g_partial[tid + 256 * i];
    red[tid] = s;
    __syncthreads();
    for (int off = 128; off > 0; off >>= 1) {
        if (tid < off) red[tid] += red[tid + off];
        __syncthreads();
    }
    float w = fmaxf(red[0] * (1.0f / 67108864.0f), EPSV);  // /(N*K)=2^26 exact
    __syncthreads();
    return w;
}

// ---------------------------------------------------------------------------
__global__ void wsum_kernel(const float* __restrict__ w) {
    __shared__ float red[256];
    const float4* w4 = reinterpret_cast<const float4*>(w);
    const size_t n4 = (size_t)NDIM * KDIM / 4;
    float s = 0.f;
    for (size_t i = (size_t)blockIdx.x * 256 + threadIdx.x; i < n4; i += (size_t)2048 * 256) {
        float4 v = w4[i];
        s += fabsf(v.x) + fabsf(v.y) + fabsf(v.z) + fabsf(v.w);
    }
    red[threadIdx.x] = s;
    __syncthreads();
    for (int off = 128; off > 0; off >>= 1) {
        if (threadIdx.x < off) red[threadIdx.x] += red[threadIdx.x + off];
        __syncthreads();
    }
    if (threadIdx.x == 0) g_partial[blockIdx.x] = red[0];
}

// ---------------------------------------------------------------------------
// Weight ternarize: rows [0,8192) -> bf16 (bf16 GEMM half),
//                   rows [8192,16384) -> int8 (int8 GEMM half)
// ---------------------------------------------------------------------------
__global__ void wquant_kernel(const float* __restrict__ w) {
    __shared__ float red[256];
    const float sc = compute_wscale(threadIdx.x, red);
    const float4* w4 = reinterpret_cast<const float4*>(w);
    __nv_bfloat162* ob = reinterpret_cast<__nv_bfloat162*>(g_wqbf);
    uchar4* o4 = reinterpret_cast<uchar4*>(g_wq);
    const size_t n4 = (size_t)NDIM * KDIM / 4;
    const size_t half4 = (size_t)NHALF * KDIM / 4;
    for (size_t i = (size_t)blockIdx.x * blockDim.x + threadIdx.x; i < n4;
         i += (size_t)gridDim.x * blockDim.x) {
        float4 v = w4[i];
        float a = fminf(fmaxf(rintf(v.x / sc), -1.f), 1.f);
        float b = fminf(fmaxf(rintf(v.y / sc), -1.f), 1.f);
        float c = fminf(fmaxf(rintf(v.z / sc), -1.f), 1.f);
        float d = fminf(fmaxf(rintf(v.w / sc), -1.f), 1.f);
        if (i < half4) {
            ob[2 * i]     = __floats2bfloat162_rn(a, b);
            ob[2 * i + 1] = __floats2bfloat162_rn(c, d);
        } else {
            size_t j = i - half4;
            o4[j] = make_uchar4((uint8_t)(int8_t)(int)a, (uint8_t)(int8_t)(int)b,
                                (uint8_t)(int8_t)(int)c, (uint8_t)(int8_t)(int)d);
        }
    }
}

// ---------------------------------------------------------------------------
// Activation quant: per-token absmax -> int8 AND bf16 copies
// ---------------------------------------------------------------------------
__global__ void xquant_kernel(const float* __restrict__ x) {
    __shared__ float red[256];
    __shared__ float s_sh;
    const float wsc = compute_wscale(threadIdx.x, red);
    const int t = blockIdx.x;
    const float4* xr = reinterpret_cast<const float4*>(x + (size_t)t * KDIM);
    float4 v[4];
    float mx = 0.f;
#pragma unroll
    for (int j = 0; j < 4; j++) {
        v[j] = xr[j * 256 + threadIdx.x];
        mx = fmaxf(mx, fmaxf(fmaxf(fabsf(v[j].x), fabsf(v[j].y)),
                             fmaxf(fabsf(v[j].z), fabsf(v[j].w))));
    }
    red[threadIdx.x] = mx;
    __syncthreads();
    for (int off = 128; off > 0; off >>= 1) {
        if (threadIdx.x < off) red[threadIdx.x] = fmaxf(red[threadIdx.x], red[threadIdx.x + off]);
        __syncthreads();
    }
    if (threadIdx.x == 0) {
        float s = fmaxf(red[0], EPSV) / 7.0f;
        s_sh = s;
        g_st[t] = s * wsc;
    }
    __syncthreads();
    const float s = s_sh;
    uchar4* o4 = reinterpret_cast<uchar4*>(g_qx + (size_t)t * KDIM);
    __nv_bfloat162* ob = reinterpret_cast<__nv_bfloat162*>(g_qxbf + (size_t)t * KDIM);
#pragma unroll
    for (int j = 0; j < 4; j++) {
        int i4 = j * 256 + threadIdx.x;
        float a = fminf(fmaxf(rintf(v[j].x / s), -8.f), 7.f);
        float b = fminf(fmaxf(rintf(v[j].y / s), -8.f), 7.f);
        float c = fminf(fmaxf(rintf(v[j].z / s), -8.f), 7.f);
        float d = fminf(fmaxf(rintf(v[j].w / s), -8.f), 7.f);
        o4[i4] = make_uchar4((uint8_t)(int8_t)(int)a, (uint8_t)(int8_t)(int)b,
                             (uint8_t)(int8_t)(int)c, (uint8_t)(int8_t)(int)d);
        ob[2 * i4]     = __floats2bfloat162_rn(a, b);
        ob[2 * i4 + 1] = __floats2bfloat162_rn(c, d);
    }
}

// ===========================================================================
// Shared GEMM geometry: BM=BN=128, 64B smem rows (16B-chunk XOR swizzle),
// 5 stages x 16KB = 81920B smem, 8 warps (2x4), warp tile 64x32.
// int8: 64B row = k64 bytes (2 x k32 steps), KT=64.
// bf16: 64B row = 32 elems (2 x k16 steps), KT=128.
// ===========================================================================
static constexpr int BM = 128, BN = 128, STAGES = 5;
static constexpr int STAGE_BYTES = (BM + BN) * 64;      // 16384
static constexpr int SMEM_GEMM = STAGES * STAGE_BYTES;  // 81920

__device__ __forceinline__ uint32_t swz(int row, int chunk) {
    return (uint32_t)(row * 64 + ((chunk ^ ((row >> 1) & 3)) << 4));
}

#define LDSM_X4(R0, R1, R2, R3, ADDR)                                          \
    asm volatile("ldmatrix.sync.aligned.m8n8.x4.shared.b16 {%0,%1,%2,%3}, [%4];" \
                 : "=r"(R0), "=r"(R1), "=r"(R2), "=r"(R3) : "r"(ADDR))

#define MMA_S8(C, A, B0, B1)                                                   \
    asm volatile(                                                              \
        "mma.sync.aligned.m16n8k32.row.col.s32.s8.s8.s32 "                     \
        "{%0,%1,%2,%3}, {%4,%5,%6,%7}, {%8,%9}, {%0,%1,%2,%3};"                \
        : "+r"((C)[0]), "+r"((C)[1]), "+r"((C)[2]), "+r"((C)[3])               \
        : "r"((A)[0]), "r"((A)[1]), "r"((A)[2]), "r"((A)[3]), "r"(B0), "r"(B1))

#define MMA_BF16(C, A, B0, B1)                                                 \
    asm volatile(                                                              \
        "mma.sync.aligned.m16n8k16.row.col.f32.bf16.bf16.f32 "                 \
        "{%0,%1,%2,%3}, {%4,%5,%6,%7}, {%8,%9}, {%0,%1,%2,%3};"                \
        : "+f"((C)[0]), "+f"((C)[1]), "+f"((C)[2]), "+f"((C)[3])               \
        : "r"((A)[0]), "r"((A)[1]), "r"((A)[2]), "r"((A)[3]), "r"(B0), "r"(B1))

// GEMM body generator: ELEM = int8_t or __nv_bfloat16; MMAOP consumes one
// 16B-chunk-pair step. ROW_ELEMS = elements per 64B row.
template <typename ELEM, typename ACC, int KT_, bool IS_BF16>
__device__ __forceinline__ void gemm_body(
    float* __restrict__ out, const ELEM* __restrict__ gqx, const ELEM* __restrict__ gw,
    int n_off, uint32_t sb) {
    const int tid = threadIdx.x;
    const int wid = tid >> 5;
    const int lane = tid & 31;
    const int warp_m = wid >> 2;
    const int warp_n = wid & 3;
    constexpr int ROW_ELEMS = IS_BF16 ? 32 : 64;

    const int num_n = NHALF / BN;  // 64
    int pid = blockIdx.x;
    int group = pid / (8 * num_n);
    int pid_m = group * 8 + (pid % 8);
    int pid_n = (pid % (8 * num_n)) / 8;
    const int m_base = pid_m * BM;
    const int n_base = n_off + pid_n * BN;
    const int n_loc = pid_n * BN;          // weight array starts at its half

    const int lrow = tid >> 1;
    const int lc = (tid & 1) * 2;
    const ELEM* ga = gqx + (size_t)(m_base + lrow) * KDIM + lc * (16 / sizeof(ELEM));
    const ELEM* gb = gw + (size_t)(n_loc + lrow) * KDIM + lc * (16 / sizeof(ELEM));
    const uint32_t sa0 = swz(lrow, lc), sa1 = swz(lrow, lc + 1);

    auto load_tile = [&](int s, int k) {
        const uint32_t st = sb + s * STAGE_BYTES;
        const ELEM* a = ga + (size_t)k * ROW_ELEMS;
        const ELEM* b = gb + (size_t)k * ROW_ELEMS;
        asm volatile("cp.async.cg.shared.global [%0], [%1], 16;" :: "r"(st + sa0), "l"(a) : "memory");
        asm volatile("cp.async.cg.shared.global [%0], [%1], 16;" :: "r"(st + sa1), "l"((const char*)a + 16) : "memory");
        asm volatile("cp.async.cg.shared.global [%0], [%1], 16;" :: "r"(st + BM * 64 + sa0), "l"(b) : "memory");
        asm volatile("cp.async.cg.shared.global [%0], [%1], 16;" :: "r"(st + BM * 64 + sa1), "l"((const char*)b + 16) : "memory");
        asm volatile("cp.async.commit_group;" ::: "memory");
    };

    const int ra = (lane & 7) + ((lane >> 3) & 1) * 8;
    const int csel = lane >> 4;

    uint32_t a_rowterm[4]; int a_swz[4];
#pragma unroll
    for (int i = 0; i < 4; i++) {
        int r = warp_m * 64 + i * 16 + ra;
        a_rowterm[i] = (uint32_t)(r * 64);
        a_swz[i] = (r >> 1) & 3;
    }
    uint32_t b_rowterm[2]; int b_swz[2];
#pragma unroll
    for (int j = 0; j < 2; j++) {
        int r = warp_n * 32 + j * 16 + ra;
        b_rowterm[j] = (uint32_t)(BM * 64 + r * 64);
        b_swz[j] = (r >> 1) & 3;
    }

    ACC acc[4][4][4];
#pragma unroll
    for (int i = 0; i < 4; i++)
#pragma unroll
        for (int j = 0; j < 4; j++)
#pragma unroll
            for (int c = 0; c < 4; c++) acc[i][j][c] = (ACC)0;

#pragma unroll
    for (int p = 0; p < STAGES - 1; p++) load_tile(p, p);

    int stage_c = 0, stage_p = STAGES - 1;
    for (int k = 0; k < KT_; k++) {
        asm volatile("cp.async.wait_group %0;" :: "n"(STAGES - 2) : "memory");
        __syncthreads();
        if (k + STAGES - 1 < KT_) load_tile(stage_p, k + STAGES - 1);
        else asm volatile("cp.async.commit_group;" ::: "memory");
        if (++stage_p == STAGES) stage_p = 0;

        const uint32_t st = sb + stage_c * STAGE_BYTES;
        if (++stage_c == STAGES) stage_c = 0;
#pragma unroll
        for (int ks = 0; ks < 2; ks++) {
            const int cbase = ks * 2 + csel;
            uint32_t afr[4][4];
#pragma unroll
            for (int i = 0; i < 4; i++) {
                uint32_t addr = st + a_rowterm[i] + (uint32_t)((cbase ^ a_swz[i]) << 4);
                LDSM_X4(afr[i][0], afr[i][1], afr[i][2], afr[i][3], addr);
            }
            uint32_t bfr[2][4];
#pragma unroll
            for (int j = 0; j < 2; j++) {
                uint32_t addr = st + b_rowterm[j] + (uint32_t)((cbase ^ b_swz[j]) << 4);
                LDSM_X4(bfr[j][0], bfr[j][1], bfr[j][2], bfr[j][3], addr);
            }
#pragma unroll
            for (int i = 0; i < 4; i++) {
#pragma unroll
                for (int j = 0; j < 2; j++) {
                    if constexpr (IS_BF16) {
                        MMA_BF16(acc[i][2 * j],     afr[i], bfr[j][0], bfr[j][2]);
                        MMA_BF16(acc[i][2 * j + 1], afr[i], bfr[j][1], bfr[j][3]);
                    } else {
                        MMA_S8(acc[i][2 * j],     afr[i], bfr[j][0], bfr[j][2]);
                        MMA_S8(acc[i][2 * j + 1], afr[i], bfr[j][1], bfr[j][3]);
                    }
                }
            }
        }
    }

#pragma unroll
    for (int i = 0; i < 4; i++) {
        const int r0 = m_base + warp_m * 64 + i * 16 + (lane >> 2);
        const int r1 = r0 + 8;
        const float st0 = g_st[r0];
        const float st1 = g_st[r1];
        float* o0 = out + (size_t)r0 * NDIM + n_base + warp_n * 32 + (lane & 3) * 2;
        float* o1 = out + (size_t)r1 * NDIM + n_base + warp_n * 32 + (lane & 3) * 2;
#pragma unroll
        for (int j = 0; j < 4; j++) {
            float2 v0 = make_float2((float)acc[i][j][0] * st0, (float)acc[i][j][1] * st0);
            float2 v1 = make_float2((float)acc[i][j][2] * st1, (float)acc[i][j][3] * st1);
            *reinterpret_cast<float2*>(o0 + j * 8) = v0;
            *reinterpret_cast<float2*>(o1 + j * 8) = v1;
        }
    }
}

__global__ void __launch_bounds__(256, 1)
gemm_bf16_kernel(float* __restrict__ out) {
    extern __shared__ char smem[];
    gemm_body<__nv_bfloat16, float, KDIM / 32, true>(out, g_qxbf, g_wqbf, 0, smem_u32(smem));
}

__global__ void __launch_bounds__(256, 1)
gemm_s8_kernel(float* __restrict__ out) {
    extern __shared__ char smem[];
    gemm_body<int8_t, int, KDIM / 64, false>(out, g_qx, g_wq, NHALF, smem_u32(smem));
}

// ---------------------------------------------------------------------------
extern "C" void kernel_launch(void* const* d_in, const int* in_sizes, int n_in,
                              void* d_out, int out_size) {
    const float* x = (const float*)d_in[0];
    const float* w = (const float*)d_in[1];
    if (n_in >= 2 && in_sizes[0] > in_sizes[1]) {
        const float* t = x; x = w; w = t;
    }
    float* out = (float*)d_out;

    wsum_kernel<<<2048, 256>>>(w);                       // idx 0
    wquant_kernel<<<8192, 256>>>(w);                     // idx 1
    xquant_kernel<<<MDIM, 256>>>(x);                     // idx 2

    cudaFuncSetAttribute(gemm_bf16_kernel, cudaFuncAttributeMaxDynamicSharedMemorySize, SMEM_GEMM);
    cudaFuncSetAttribute(gemm_s8_kernel, cudaFuncAttributeMaxDynamicSharedMemorySize, SMEM_GEMM);
    const int half_grid = (MDIM / BM) * (NHALF / BN);    // 4096
    gemm_bf16_kernel<<<half_grid, 256, SMEM_GEMM>>>(out);  // idx 3 (ncu capture)
    gemm_s8_kernel<<<half_grid, 256, SMEM_GEMM>>>(out);    // idx 4
}

// round 12
// speedup vs baseline: 1.9892x; 1.4937x over previous
#include <cuda_runtime.h>
#include <cuda_bf16.h>
#include <cstdint>
#include <cstddef>

// ============================================================================
// BitLinear, all-bf16 HMMA edition (proven-envelope config):
//   out[m,n] = (sum_k qx[m,k]*t[n,k]) * s_tok[m] * s_w
//   qx in [-8,7], t in {-1,0,1} held exactly in bf16; f32 accum exact.
// GEMM kernel is byte-identical in structure to the round-8 PASSING bf16
// instantiation: 5 stages, 81920B smem, __launch_bounds__(256,1).
// Launched twice (N halves). int8 path deleted (was 2x slower per half).
// ============================================================================

static constexpr int MDIM = 8192;
static constexpr int NDIM = 16384;
static constexpr int KDIM = 4096;
static constexpr int NHALF = NDIM / 2;
static constexpr float EPSV = 1e-5f;

__device__ __align__(128) __nv_bfloat16 g_qxbf[(size_t)MDIM * KDIM];   // 67 MB
__device__ __align__(128) __nv_bfloat16 g_wqbf[(size_t)NDIM * KDIM];   // 134 MB
__device__ float g_st[MDIM];
__device__ float g_partial[2048];

__device__ __forceinline__ uint32_t smem_u32(const void* p) {
    uint32_t a;
    asm("{ .reg .u64 t; cvta.to.shared.u64 t, %1; cvt.u32.u64 %0, t; }" : "=r"(a) : "l"(p));
    return a;
}

// Deterministic inline reduction of g_partial -> wscale (identical in all users)
__device__ __forceinline__ float compute_wscale(int tid, float* red) {
    float s = 0.f;
#pragma unroll
    for (int i = 0; i < 8; i++) s += g_partial[tid + 256 * i];
    red[tid] = s;
    __syncthreads();
    for (int off = 128; off > 0; off >>= 1) {
        if (tid < off) red[tid] += red[tid + off];
        __syncthreads();
    }
    float w = fmaxf(red[0] * (1.0f / 67108864.0f), EPSV);  // /(N*K)=2^26 exact
    __syncthreads();
    return w;
}

// ---------------------------------------------------------------------------
__global__ void wsum_kernel(const float* __restrict__ w) {
    __shared__ float red[256];
    const float4* w4 = reinterpret_cast<const float4*>(w);
    const size_t n4 = (size_t)NDIM * KDIM / 4;
    float s = 0.f;
    for (size_t i = (size_t)blockIdx.x * 256 + threadIdx.x; i < n4; i += (size_t)2048 * 256) {
        float4 v = w4[i];
        s += fabsf(v.x) + fabsf(v.y) + fabsf(v.z) + fabsf(v.w);
    }
    red[threadIdx.x] = s;
    __syncthreads();
    for (int off = 128; off > 0; off >>= 1) {
        if (threadIdx.x < off) red[threadIdx.x] += red[threadIdx.x + off];
        __syncthreads();
    }
    if (threadIdx.x == 0) g_partial[blockIdx.x] = red[0];
}

// ---------------------------------------------------------------------------
// Weight ternarize -> bf16 {-1,0,1}
// ---------------------------------------------------------------------------
__global__ void wquant_kernel(const float* __restrict__ w) {
    __shared__ float red[256];
    const float sc = compute_wscale(threadIdx.x, red);
    const float4* w4 = reinterpret_cast<const float4*>(w);
    __nv_bfloat162* ob = reinterpret_cast<__nv_bfloat162*>(g_wqbf);
    const size_t n4 = (size_t)NDIM * KDIM / 4;
    for (size_t i = (size_t)blockIdx.x * blockDim.x + threadIdx.x; i < n4;
         i += (size_t)gridDim.x * blockDim.x) {
        float4 v = w4[i];
        float a = fminf(fmaxf(rintf(v.x / sc), -1.f), 1.f);
        float b = fminf(fmaxf(rintf(v.y / sc), -1.f), 1.f);
        float c = fminf(fmaxf(rintf(v.z / sc), -1.f), 1.f);
        float d = fminf(fmaxf(rintf(v.w / sc), -1.f), 1.f);
        ob[2 * i]     = __floats2bfloat162_rn(a, b);
        ob[2 * i + 1] = __floats2bfloat162_rn(c, d);
    }
}

// ---------------------------------------------------------------------------
// Activation quant: per-token absmax -> bf16 ints in [-8,7]
// ---------------------------------------------------------------------------
__global__ void xquant_kernel(const float* __restrict__ x) {
    __shared__ float red[256];
    __shared__ float s_sh;
    const float wsc = compute_wscale(threadIdx.x, red);
    const int t = blockIdx.x;
    const float4* xr = reinterpret_cast<const float4*>(x + (size_t)t * KDIM);
    float4 v[4];
    float mx = 0.f;
#pragma unroll
    for (int j = 0; j < 4; j++) {
        v[j] = xr[j * 256 + threadIdx.x];
        mx = fmaxf(mx, fmaxf(fmaxf(fabsf(v[j].x), fabsf(v[j].y)),
                             fmaxf(fabsf(v[j].z), fabsf(v[j].w))));
    }
    red[threadIdx.x] = mx;
    __syncthreads();
    for (int off = 128; off > 0; off >>= 1) {
        if (threadIdx.x < off) red[threadIdx.x] = fmaxf(red[threadIdx.x], red[threadIdx.x + off]);
        __syncthreads();
    }
    if (threadIdx.x == 0) {
        float s = fmaxf(red[0], EPSV) / 7.0f;
        s_sh = s;
        g_st[t] = s * wsc;
    }
    __syncthreads();
    const float s = s_sh;
    __nv_bfloat162* ob = reinterpret_cast<__nv_bfloat162*>(g_qxbf + (size_t)t * KDIM);
#pragma unroll
    for (int j = 0; j < 4; j++) {
        int i4 = j * 256 + threadIdx.x;
        float a = fminf(fmaxf(rintf(v[j].x / s), -8.f), 7.f);
        float b = fminf(fmaxf(rintf(v[j].y / s), -8.f), 7.f);
        float c = fminf(fmaxf(rintf(v[j].z / s), -8.f), 7.f);
        float d = fminf(fmaxf(rintf(v[j].w / s), -8.f), 7.f);
        ob[2 * i4]     = __floats2bfloat162_rn(a, b);
        ob[2 * i4 + 1] = __floats2bfloat162_rn(c, d);
    }
}

// ===========================================================================
// bf16 GEMM (round-8 proven config): BM=BN=128, 64B smem rows (32 bf16 =
// 2 x k16 steps), KT=128, 5 stages x 16KB = 81920B smem, 8 warps (2x4),
// warp tile 64x32, __launch_bounds__(256,1).
// ===========================================================================
static constexpr int BM = 128, BN = 128, STAGES = 5;
static constexpr int STAGE_BYTES = (BM + BN) * 64;      // 16384
static constexpr int SMEM_GEMM = STAGES * STAGE_BYTES;  // 81920
static constexpr int KT = KDIM / 32;                    // 128 iters

__device__ __forceinline__ uint32_t swz(int row, int chunk) {
    return (uint32_t)(row * 64 + ((chunk ^ ((row >> 1) & 3)) << 4));
}

#define LDSM_X4(R0, R1, R2, R3, ADDR)                                          \
    asm volatile("ldmatrix.sync.aligned.m8n8.x4.shared.b16 {%0,%1,%2,%3}, [%4];" \
                 : "=r"(R0), "=r"(R1), "=r"(R2), "=r"(R3) : "r"(ADDR))

#define MMA_BF16(C, A, B0, B1)                                                 \
    asm volatile(                                                              \
        "mma.sync.aligned.m16n8k16.row.col.f32.bf16.bf16.f32 "                 \
        "{%0,%1,%2,%3}, {%4,%5,%6,%7}, {%8,%9}, {%0,%1,%2,%3};"                \
        : "+f"((C)[0]), "+f"((C)[1]), "+f"((C)[2]), "+f"((C)[3])               \
        : "r"((A)[0]), "r"((A)[1]), "r"((A)[2]), "r"((A)[3]), "r"(B0), "r"(B1))

__global__ void __launch_bounds__(256, 1)
gemm_bf16_kernel(float* __restrict__ out, int n_off) {
    extern __shared__ char smem[];
    const uint32_t sb = smem_u32(smem);
    const int tid = threadIdx.x;
    const int wid = tid >> 5;
    const int lane = tid & 31;
    const int warp_m = wid >> 2;
    const int warp_n = wid & 3;

    const int num_n = NHALF / BN;  // 64
    int pid = blockIdx.x;
    int group = pid / (8 * num_n);
    int pid_m = group * 8 + (pid % 8);
    int pid_n = (pid % (8 * num_n)) / 8;
    const int m_base = pid_m * BM;
    const int n_base = n_off + pid_n * BN;

    const int lrow = tid >> 1;
    const int lc = (tid & 1) * 2;
    const __nv_bfloat16* ga = g_qxbf + (size_t)(m_base + lrow) * KDIM + lc * 8;
    const __nv_bfloat16* gb = g_wqbf + (size_t)(n_base + lrow) * KDIM + lc * 8;
    const uint32_t sa0 = swz(lrow, lc), sa1 = swz(lrow, lc + 1);

    auto load_tile = [&](int s, int k) {
        const uint32_t st = sb + s * STAGE_BYTES;
        const __nv_bfloat16* a = ga + (size_t)k * 32;
        const __nv_bfloat16* b = gb + (size_t)k * 32;
        asm volatile("cp.async.cg.shared.global [%0], [%1], 16;" :: "r"(st + sa0), "l"(a) : "memory");
        asm volatile("cp.async.cg.shared.global [%0], [%1], 16;" :: "r"(st + sa1), "l"(a + 8) : "memory");
        asm volatile("cp.async.cg.shared.global [%0], [%1], 16;" :: "r"(st + BM * 64 + sa0), "l"(b) : "memory");
        asm volatile("cp.async.cg.shared.global [%0], [%1], 16;" :: "r"(st + BM * 64 + sa1), "l"(b + 8) : "memory");
        asm volatile("cp.async.commit_group;" ::: "memory");
    };

    const int ra = (lane & 7) + ((lane >> 3) & 1) * 8;
    const int csel = lane >> 4;

    uint32_t a_rowterm[4]; int a_swz[4];
#pragma unroll
    for (int i = 0; i < 4; i++) {
        int r = warp_m * 64 + i * 16 + ra;
        a_rowterm[i] = (uint32_t)(r * 64);
        a_swz[i] = (r >> 1) & 3;
    }
    uint32_t b_rowterm[2]; int b_swz[2];
#pragma unroll
    for (int j = 0; j < 2; j++) {
        int r = warp_n * 32 + j * 16 + ra;
        b_rowterm[j] = (uint32_t)(BM * 64 + r * 64);
        b_swz[j] = (r >> 1) & 3;
    }

    float acc[4][4][4];
#pragma unroll
    for (int i = 0; i < 4; i++)
#pragma unroll
        for (int j = 0; j < 4; j++)
#pragma unroll
            for (int c = 0; c < 4; c++) acc[i][j][c] = 0.f;

#pragma unroll
    for (int p = 0; p < STAGES - 1; p++) load_tile(p, p);

    int stage_c = 0, stage_p = STAGES - 1;
    for (int k = 0; k < KT; k++) {
        asm volatile("cp.async.wait_group %0;" :: "n"(STAGES - 2) : "memory");
        __syncthreads();
        if (k + STAGES - 1 < KT) load_tile(stage_p, k + STAGES - 1);
        else asm volatile("cp.async.commit_group;" ::: "memory");
        if (++stage_p == STAGES) stage_p = 0;

        const uint32_t st = sb + stage_c * STAGE_BYTES;
        if (++stage_c == STAGES) stage_c = 0;
#pragma unroll
        for (int ks = 0; ks < 2; ks++) {
            const int cbase = ks * 2 + csel;
            uint32_t afr[4][4];
#pragma unroll
            for (int i = 0; i < 4; i++) {
                uint32_t addr = st + a_rowterm[i] + (uint32_t)((cbase ^ a_swz[i]) << 4);
                LDSM_X4(afr[i][0], afr[i][1], afr[i][2], afr[i][3], addr);
            }
            uint32_t bfr[2][4];
#pragma unroll
            for (int j = 0; j < 2; j++) {
                uint32_t addr = st + b_rowterm[j] + (uint32_t)((cbase ^ b_swz[j]) << 4);
                LDSM_X4(bfr[j][0], bfr[j][1], bfr[j][2], bfr[j][3], addr);
            }
#pragma unroll
            for (int i = 0; i < 4; i++) {
#pragma unroll
                for (int j = 0; j < 2; j++) {
                    MMA_BF16(acc[i][2 * j],     afr[i], bfr[j][0], bfr[j][2]);
                    MMA_BF16(acc[i][2 * j + 1], afr[i], bfr[j][1], bfr[j][3]);
                }
            }
        }
    }

#pragma unroll
    for (int i = 0; i < 4; i++) {
        const int r0 = m_base + warp_m * 64 + i * 16 + (lane >> 2);
        const int r1 = r0 + 8;
        const float st0 = g_st[r0];
        const float st1 = g_st[r1];
        float* o0 = out + (size_t)r0 * NDIM + n_base + warp_n * 32 + (lane & 3) * 2;
        float* o1 = out + (size_t)r1 * NDIM + n_base + warp_n * 32 + (lane & 3) * 2;
#pragma unroll
        for (int j = 0; j < 4; j++) {
            float2 v0 = make_float2(acc[i][j][0] * st0, acc[i][j][1] * st0);
            float2 v1 = make_float2(acc[i][j][2] * st1, acc[i][j][3] * st1);
            *reinterpret_cast<float2*>(o0 + j * 8) = v0;
            *reinterpret_cast<float2*>(o1 + j * 8) = v1;
        }
    }
}

// ---------------------------------------------------------------------------
extern "C" void kernel_launch(void* const* d_in, const int* in_sizes, int n_in,
                              void* d_out, int out_size) {
    const float* x = (const float*)d_in[0];
    const float* w = (const float*)d_in[1];
    if (n_in >= 2 && in_sizes[0] > in_sizes[1]) {
        const float* t = x; x = w; w = t;
    }
    float* out = (float*)d_out;

    wsum_kernel<<<2048, 256>>>(w);                       // idx 0
    wquant_kernel<<<8192, 256>>>(w);                     // idx 1
    xquant_kernel<<<MDIM, 256>>>(x);                     // idx 2

    cudaFuncSetAttribute(gemm_bf16_kernel, cudaFuncAttributeMaxDynamicSharedMemorySize, SMEM_GEMM);
    const int half_grid = (MDIM / BM) * (NHALF / BN);    // 4096
    gemm_bf16_kernel<<<half_grid, 256, SMEM_GEMM>>>(out, 0);      // idx 3 (ncu)
    gemm_bf16_kernel<<<half_grid, 256, SMEM_GEMM>>>(out, NHALF);  // idx 4
}